// round 14
// baseline (speedup 1.0000x reference)
#include <cuda_runtime.h>

#define NF 40
#define KS 401
#define LEN 160000
#define NB 8
#define T_OUT 1000
#define PSTRIDE 160
#define RPT 9
#define FPAD 416

// fused-kernel geometry: 64 pool outputs per chunk, 512 threads
#define NTHR 512
#define CH_OUTS 64
#define N_CHUNK 16                       // 16*64 = 1024 >= 1000
#define YS_N 10481                       // 64*160 + 401 - 160
#define XS_N 11008
#define PASS_W (NTHR * RPT)              // 4608 outputs per full pass
#define TAIL_BASE (2 * PASS_W)           // 9216; tail R=3 covers [9216,10752)

typedef unsigned long long ull;

// ---------------- device scratch ----------------
__device__ float  d_frames[NB * NF * T_OUT];
__device__ float  d_Ms[NB * NF * T_OUT];
__device__ float2 d_filt2[NF * FPAD];
__device__ float  d_win[NF * KS];
__device__ int    d_klo[NF], d_kend[NF];

// ---------------- helpers ----------------
__device__ __forceinline__ ull ffma2(ull a, ull b, ull c) {
    ull d;
    asm("fma.rn.f32x2 %0, %1, %2, %3;" : "=l"(d) : "l"(a), "l"(b), "l"(c));
    return d;
}
__device__ __forceinline__ void unpack2(ull a, float& lo, float& hi) {
    asm("mov.b64 {%0, %1}, %2;" : "=f"(lo), "=f"(hi) : "l"(a));
}
__device__ __forceinline__ float sigmoidf_(float x) {
    return __fdividef(1.f, 1.f + __expf(-x));
}
__device__ __forceinline__ float tanhf_(float x) {
    return 1.f - __fdividef(2.f, __expf(2.f * x) + 1.f);
}

// ---------------- Kernel A: build filters ----------------
__global__ void build_filters(const float* __restrict__ cfr,
                              const float* __restrict__ bwr,
                              const float* __restrict__ pwr) {
    int f = blockIdx.x, tid = threadIdx.x;
    const float Z = 0.3747739708f;
    const float PI_F = 3.14159265358979f;
    float cf = fminf(fmaxf(cfr[f], 0.f), PI_F);
    float bw = fminf(fmaxf(bwr[f], 4.f * Z), 401.f * Z);
    float pw = fminf(fmaxf(pwr[f], 2.f / 401.f), 0.5f);
    float denom = 1.f / (sqrtf(2.f * PI_F) * bw);
    float inv2bw2 = 1.f / (2.f * bw * bw);
    float invpw = 1.f / pw;

    int R = (int)ceilf(4.0f * bw);       // 4.0 sigma truncation (tail ~6e-5)
    if (R > 200) R = 200;
    int klo = 200 - R, khi = 200 + R;

    for (int i = tid; i < FPAD; i += blockDim.x)
        d_filt2[f * FPAD + i] = make_float2(0.f, 0.f);
    __syncthreads();
    for (int k = tid; k < KS; k += blockDim.x) {
        float t = (float)(k - 200);
        float tt = (float)k / 400.f - 0.5f;
        d_win[f * KS + k] = expf(-0.5f * tt * tt * invpw * invpw);
        if (k >= klo && k <= khi) {
            float g = expf(-t * t * inv2bw2);
            float s, c;
            sincosf(cf * t, &s, &c);
            d_filt2[f * FPAD + k] = make_float2(denom * g * c, denom * g * s);
        }
    }
    if (tid == 0) {
        int span = khi - klo + 1;
        int kend = klo + RPT * ((span + RPT - 1) / RPT);  // span multiple of 9
        d_klo[f] = klo;
        d_kend[f] = kend;                                 // max 405 < FPAD
    }
}

// ---------------- conv pass: R outputs/thread, MOV-free (x duplicated) --------
// xs2[i] = (x_i, x_i) packed; refill = single LDS.64. Requires (kend-klo)%R==0.
template <int R>
__device__ __forceinline__ void conv_pass(const ull* __restrict__ xs2,
                                          const float2* __restrict__ fsh,
                                          float* __restrict__ ys,
                                          int i0, int gy0, int klo, int kend) {
    if (i0 >= YS_N) return;
    int g0 = gy0 + i0;
    if (g0 >= LEN) {
        #pragma unroll
        for (int r = 0; r < R; r++)
            if (i0 + r < YS_N) ys[i0 + r] = 0.f;
        return;
    }
    ull w[R], acc[R];
    #pragma unroll
    for (int r = 0; r < R; r++) {
        acc[r] = 0ull;
        w[r] = xs2[i0 + klo + r];
    }
    for (int k = klo; k < kend; k += R) {
        #pragma unroll
        for (int j = 0; j < R; j++) {
            ull fv = *(const ull*)&fsh[k + j];       // (fr,fi) broadcast
            #pragma unroll
            for (int r = 0; r < R; r++)
                acc[r] = ffma2(w[(j + r) % R], fv, acc[r]);
            w[j] = xs2[i0 + k + j + R];              // MOV-free refill
        }
    }
    #pragma unroll
    for (int r = 0; r < R; r++) {
        int i = i0 + r;
        if (i < YS_N) {
            int g = g0 + r;
            float re, im;
            unpack2(acc[r], re, im);
            ys[i] = (g >= 0 && g < LEN) ? (re * re + im * im) : 0.f;
        }
    }
}

// ---------------- Kernel B: fused Gabor conv + |.|^2 + Gaussian pooling --------
__global__ __launch_bounds__(NTHR, 1) void gabor_fused(const float* __restrict__ x) {
    int chunk = blockIdx.x, f = blockIdx.y, b = blockIdx.z;
    int tid = threadIdx.x;

    extern __shared__ __align__(16) char smem_c[];
    ull*    xs2  = (ull*)smem_c;                          // [XS_N]  88064 B
    float2* fsh  = (float2*)(smem_c + XS_N * 8);          // [FPAD]  3328 B
    float*  win  = (float*)(smem_c + XS_N * 8 + FPAD * 8);          // [FPAD] 1664 B
    float*  ys   = (float*)(smem_c + XS_N * 8 + FPAD * 12);         // [YS_N..] 41984 B
    float*  part = ys + 10496;                            // [512]

    const float* xrow = x + b * LEN;
    int gx0 = chunk * (CH_OUTS * PSTRIDE) - 400;
    int gy0 = chunk * (CH_OUTS * PSTRIDE) - 200;

    for (int i = tid; i < XS_N; i += NTHR) {
        int g = gx0 + i;
        float v = (g >= 0 && g < LEN) ? xrow[g] : 0.f;
        ((float2*)xs2)[i] = make_float2(v, v);
    }
    for (int i = tid; i < FPAD; i += NTHR) {
        fsh[i] = d_filt2[f * FPAD + i];
        win[i] = (i < KS) ? d_win[f * KS + i] : 0.f;
    }
    __syncthreads();

    int klo = d_klo[f], kend = d_kend[f];

    conv_pass<RPT>(xs2, fsh, ys, 0 * PASS_W + tid * RPT, gy0, klo, kend);
    conv_pass<RPT>(xs2, fsh, ys, 1 * PASS_W + tid * RPT, gy0, klo, kend);
    conv_pass<3>(xs2, fsh, ys, TAIL_BASE + tid * 3, gy0, klo, kend);
    __syncthreads();

    // ---- pooling: 8 threads per output, taps split 7x50 + 51 -----------------
    {
        int q = tid >> 6, o = tid & 63, lane = tid & 31;
        int kbase = q * 50;
        int cnt = (q == 7) ? 51 : 50;
        int off = o * PSTRIDE;
        float acc = 0.f;
        int kk = lane % cnt;
        for (int jj = 0; jj < cnt; jj++) {
            int k = kbase + kk;
            acc = fmaf(win[k], ys[off + k], acc);
            kk++;
            if (kk == cnt) kk = 0;
        }
        part[tid] = acc;
    }
    __syncthreads();
    if (tid < CH_OUTS) {
        int t = chunk * CH_OUTS + tid;
        if (t < T_OUT) {
            float s = 0.f;
            #pragma unroll
            for (int q = 0; q < 8; q++) s += part[tid + 64 * q];
            d_frames[(b * NF + f) * T_OUT + t] = s;
        }
    }
}

// ---------------- Kernel D: parallel EMA scan (warp per row) ----------------
__global__ void pcen_scan() {
    int row = blockIdx.x;
    int lane = threadIdx.x;
    const float* Fp = d_frames + row * T_OUT;
    float* Mp = d_Ms + row * T_OUT;

    int start = lane * 32;
    int n = T_OUT - start;
    if (n > 32) n = 32;
    if (n < 0) n = 0;

    float Bv = 0.f, Av = 1.f;
    for (int j = 0; j < n; j++) {
        Bv = fmaf(0.96f, Bv, 0.04f * Fp[start + j]);
        Av *= 0.96f;
    }
    for (int d = 1; d < 32; d <<= 1) {
        float Ap = __shfl_up_sync(0xffffffffu, Av, d);
        float Bp = __shfl_up_sync(0xffffffffu, Bv, d);
        if (lane >= d) {
            Bv = fmaf(Av, Bp, Bv);
            Av *= Ap;
        }
    }
    float Min = __shfl_up_sync(0xffffffffu, Bv, 1);
    if (lane == 0) Min = 0.f;

    float M = Min;
    for (int j = 0; j < n; j++) {
        M = fmaf(0.96f, M, 0.04f * Fp[start + j]);
        Mp[start + j] = M;
    }
}

// ---------------- Kernel E: GRU controller + PCEN output (R8/R10 version) -----
#define EBS 128
__global__ __launch_bounds__(EBS) void pcen_ctrl(
    const float* __restrict__ w_ih, const float* __restrict__ w_hh,
    const float* __restrict__ b_ih, const float* __restrict__ b_hh,
    const float* __restrict__ hw1, const float* __restrict__ hb1,
    const float* __restrict__ hw2, const float* __restrict__ hb2,
    float* __restrict__ out) {
    __shared__ __align__(16) float whh_s[96 * 32];
    __shared__ float wih_s[96], bih_s[96], bhh_s[96];
    __shared__ __align__(16) float hw1t_s[32 * 32];  // transposed [k][m]
    __shared__ float hb1_s[32], hw2_s[64], hb2_s[2];
    __shared__ float h2s[32 * EBS];
    int tid = threadIdx.x;
    for (int i = tid; i < 3072; i += EBS) whh_s[i] = w_hh[i];
    for (int i = tid; i < 96; i += EBS) {
        wih_s[i] = w_ih[i]; bih_s[i] = b_ih[i]; bhh_s[i] = b_hh[i];
    }
    for (int i = tid; i < 1024; i += EBS) {
        int k = i >> 5, m = i & 31;
        hw1t_s[i] = hw1[m * 32 + k];
    }
    for (int i = tid; i < 32; i += EBS) hb1_s[i] = hb1[i];
    if (tid < 64) hw2_s[tid] = hw2[tid];
    if (tid < 2) hb2_s[tid] = hb2[tid];
    __syncthreads();

    int id = blockIdx.x * EBS + tid;        // 2500*128 = 320000 exact
    int t = id % T_OUT, bf = id / T_OUT;
    float X  = d_frames[bf * T_OUT + t];
    float Xp = d_frames[bf * T_OUT + (t ? t - 1 : 0)];
    float M  = d_Ms[id];

    float h1[32];
    #pragma unroll
    for (int j = 0; j < 32; j++) {
        float r1 = sigmoidf_(fmaf(Xp, wih_s[j], bih_s[j]) + bhh_s[j]);
        float z1 = sigmoidf_(fmaf(Xp, wih_s[32 + j], bih_s[32 + j]) + bhh_s[32 + j]);
        float n1 = tanhf_(fmaf(r1, bhh_s[64 + j], fmaf(Xp, wih_s[64 + j], bih_s[64 + j])));
        h1[j] = (1.f - z1) * n1;
    }
    #pragma unroll 1
    for (int j = 0; j < 32; j++) {
        float ar = bhh_s[j], az = bhh_s[32 + j], an = bhh_s[64 + j];
        const float4* wr = (const float4*)&whh_s[j * 32];
        const float4* wz = (const float4*)&whh_s[(32 + j) * 32];
        const float4* wn = (const float4*)&whh_s[(64 + j) * 32];
        #pragma unroll
        for (int k4 = 0; k4 < 8; k4++) {
            float4 a = wr[k4], bb = wz[k4], c = wn[k4];
            ar = fmaf(a.x, h1[4*k4], ar);   ar = fmaf(a.y, h1[4*k4+1], ar);
            ar = fmaf(a.z, h1[4*k4+2], ar); ar = fmaf(a.w, h1[4*k4+3], ar);
            az = fmaf(bb.x, h1[4*k4], az);   az = fmaf(bb.y, h1[4*k4+1], az);
            az = fmaf(bb.z, h1[4*k4+2], az); az = fmaf(bb.w, h1[4*k4+3], az);
            an = fmaf(c.x, h1[4*k4], an);   an = fmaf(c.y, h1[4*k4+1], an);
            an = fmaf(c.z, h1[4*k4+2], an); an = fmaf(c.w, h1[4*k4+3], an);
        }
        float r = sigmoidf_(fmaf(X, wih_s[j], bih_s[j]) + ar);
        float z = sigmoidf_(fmaf(X, wih_s[32 + j], bih_s[32 + j]) + az);
        float n = tanhf_(fmaf(r, an, fmaf(X, wih_s[64 + j], bih_s[64 + j])));
        h2s[j * EBS + tid] = (1.f - z) * n + z * h1[j];
    }
    __syncwarp();

    float hacc[32];
    #pragma unroll
    for (int m = 0; m < 32; m++) hacc[m] = hb1_s[m];
    #pragma unroll 1
    for (int k = 0; k < 32; k++) {
        float xk = h2s[k * EBS + tid];
        const float4* wt = (const float4*)&hw1t_s[k * 32];
        #pragma unroll
        for (int m4 = 0; m4 < 8; m4++) {
            float4 v = wt[m4];
            hacc[4*m4]   = fmaf(v.x, xk, hacc[4*m4]);
            hacc[4*m4+1] = fmaf(v.y, xk, hacc[4*m4+1]);
            hacc[4*m4+2] = fmaf(v.z, xk, hacc[4*m4+2]);
            hacc[4*m4+3] = fmaf(v.w, xk, hacc[4*m4+3]);
        }
    }
    float la = hb2_s[0], lb = hb2_s[1];
    #pragma unroll
    for (int m = 0; m < 32; m++) {
        float hid = fmaxf(hacc[m], 0.f);
        la = fmaf(hw2_s[m], hid, la);
        lb = fmaf(hw2_s[32 + m], hid, lb);
    }
    float alpha = sigmoidf_(la);
    float rr = fmaf(0.8f, sigmoidf_(lb), 0.2f);
    float mp = __expf(alpha * __logf(M + 1e-6f));
    float base = __fdividef(X, mp) + 2.f;
    out[id] = __expf(rr * __logf(base)) - __expf(rr * 0.6931471805599453f);
}

// ---------------- launch ----------------
extern "C" void kernel_launch(void* const* d_in, const int* in_sizes, int n_in,
                              void* d_out, int out_size) {
    const float* x    = (const float*)d_in[0];
    const float* cf   = (const float*)d_in[1];
    const float* bw   = (const float*)d_in[2];
    const float* pw   = (const float*)d_in[3];
    const float* w_ih = (const float*)d_in[4];
    const float* w_hh = (const float*)d_in[5];
    const float* b_ih = (const float*)d_in[6];
    const float* b_hh = (const float*)d_in[7];
    const float* hw1  = (const float*)d_in[8];
    const float* hb1  = (const float*)d_in[9];
    const float* hw2  = (const float*)d_in[10];
    const float* hb2  = (const float*)d_in[11];
    float* out = (float*)d_out;

    // xs2 88064 + fsh 3328 + win 1664 + ys 41984 + part 2048 = 137,088 B
    const int SMEM_BYTES = XS_N * 8 + FPAD * 12 + 10496 * 4 + NTHR * 4;
    cudaFuncSetAttribute(gabor_fused,
                         cudaFuncAttributeMaxDynamicSharedMemorySize, SMEM_BYTES);

    build_filters<<<NF, 256>>>(cf, bw, pw);
    gabor_fused<<<dim3(N_CHUNK, NF, NB), NTHR, SMEM_BYTES>>>(x);
    pcen_scan<<<NB * NF, 32>>>();
    pcen_ctrl<<<(NB * NF * T_OUT) / EBS, EBS>>>(w_ih, w_hh, b_ih, b_hh,
                                                hw1, hb1, hw2, hb2, out);
}

// round 15
// speedup vs baseline: 1.1964x; 1.1964x over previous
#include <cuda_runtime.h>

#define NF 40
#define KS 401
#define LEN 160000
#define NB 8
#define T_OUT 1000
#define PSTRIDE 160
#define RPT 9
#define FPAD 416

// fused-kernel geometry: 64 pool outputs per chunk
#define CH_OUTS 64
#define N_CHUNK 16                       // 16*64 = 1024 >= 1000
#define YS_N 10481                       // 64*160 + 401 - 160
#define YS_PAD 10496
#define XS_N 11008
#define PASS_W (256 * RPT)               // 2304 outputs per full pass
#define TAIL_BASE (4 * PASS_W)           // 9216; tail RPT=5 covers [9216,10496)

typedef unsigned long long ull;

// ---------------- device scratch ----------------
__device__ float  d_frames[NB * NF * T_OUT];
__device__ float  d_Ms[NB * NF * T_OUT];
__device__ float2 d_filt2[NF * FPAD];
__device__ float  d_win[NF * KS];
__device__ int    d_klo[NF], d_kend[NF];

// ---------------- helpers ----------------
__device__ __forceinline__ ull ffma2(ull a, ull b, ull c) {
    ull d;
    asm("fma.rn.f32x2 %0, %1, %2, %3;" : "=l"(d) : "l"(a), "l"(b), "l"(c));
    return d;
}
__device__ __forceinline__ ull dup2(float v) {
    ull d;
    asm("mov.b64 %0, {%1, %1};" : "=l"(d) : "f"(v));
    return d;
}
__device__ __forceinline__ void unpack2(ull a, float& lo, float& hi) {
    asm("mov.b64 {%0, %1}, %2;" : "=f"(lo), "=f"(hi) : "l"(a));
}
__device__ __forceinline__ float sigmoidf_(float x) {
    return __fdividef(1.f, 1.f + __expf(-x));
}
__device__ __forceinline__ float tanhf_(float x) {
    return 1.f - __fdividef(2.f, __expf(2.f * x) + 1.f);
}

// ---------------- Kernel A: build filters ----------------
__global__ void build_filters(const float* __restrict__ cfr,
                              const float* __restrict__ bwr,
                              const float* __restrict__ pwr) {
    int f = blockIdx.x, tid = threadIdx.x;
    const float Z = 0.3747739708f;
    const float PI_F = 3.14159265358979f;
    float cf = fminf(fmaxf(cfr[f], 0.f), PI_F);
    float bw = fminf(fmaxf(bwr[f], 4.f * Z), 401.f * Z);
    float pw = fminf(fmaxf(pwr[f], 2.f / 401.f), 0.5f);
    float denom = 1.f / (sqrtf(2.f * PI_F) * bw);
    float inv2bw2 = 1.f / (2.f * bw * bw);
    float invpw = 1.f / pw;

    int R = (int)ceilf(3.5f * bw);       // 3.5 sigma truncation (pred rel ~1.6e-4)
    if (R > 200) R = 200;
    int klo = 200 - R, khi = 200 + R;

    for (int i = tid; i < FPAD; i += blockDim.x)
        d_filt2[f * FPAD + i] = make_float2(0.f, 0.f);
    __syncthreads();
    for (int k = tid; k < KS; k += blockDim.x) {
        float t = (float)(k - 200);
        float tt = (float)k / 400.f - 0.5f;
        d_win[f * KS + k] = expf(-0.5f * tt * tt * invpw * invpw);
        if (k >= klo && k <= khi) {
            float g = expf(-t * t * inv2bw2);
            float s, c;
            sincosf(cf * t, &s, &c);
            d_filt2[f * FPAD + k] = make_float2(denom * g * c, denom * g * s);
        }
    }
    if (tid == 0) {
        int klo_al = klo - (klo % RPT);
        int kend = klo_al + RPT * ((khi - klo_al) / RPT + 1);
        d_klo[f] = klo_al;
        d_kend[f] = kend;
    }
}

// ---------------- conv pass (templated output-group width) ----------------
template <int R>
__device__ __forceinline__ void conv_pass(const float* __restrict__ xs,
                                          const float2* __restrict__ fsh,
                                          float* __restrict__ ys,
                                          int i0, int gy0, int klo, int kend) {
    int g0 = gy0 + i0;
    if (g0 >= LEN) {
        #pragma unroll
        for (int r = 0; r < R; r++)
            if (i0 + r < YS_N) ys[i0 + r] = 0.f;
        return;
    }
    ull w[R], acc[R];
    #pragma unroll
    for (int r = 0; r < R; r++) {
        acc[r] = 0ull;
        w[r] = dup2(xs[i0 + klo + r]);
    }
    for (int k = klo; k < kend; k += R) {
        #pragma unroll
        for (int j = 0; j < R; j++) {
            ull fv = *(const ull*)&fsh[k + j];
            #pragma unroll
            for (int r = 0; r < R; r++)
                acc[r] = ffma2(w[(j + r) % R], fv, acc[r]);
            w[j] = dup2(xs[i0 + k + j + R]);
        }
    }
    #pragma unroll
    for (int r = 0; r < R; r++) {
        int i = i0 + r;
        if (i < YS_N) {
            int g = g0 + r;
            float re, im;
            unpack2(acc[r], re, im);
            ys[i] = (g >= 0 && g < LEN) ? (re * re + im * im) : 0.f;
        }
    }
}

// ---------------- Kernel B: fused Gabor conv + |.|^2 + Gaussian pooling --------
__global__ __launch_bounds__(256) void gabor_fused(const float* __restrict__ x) {
    int chunk = blockIdx.x, f = blockIdx.y, b = blockIdx.z;
    int tid = threadIdx.x;

    extern __shared__ __align__(16) float smem_f[];
    float*  xs   = smem_f;                              // [XS_N]
    float2* fsh  = (float2*)(smem_f + XS_N);            // [FPAD]
    float*  win  = smem_f + XS_N + 2 * FPAD;            // [FPAD]
    float*  ys   = smem_f + XS_N + 3 * FPAD;            // [YS_PAD]
    float*  part = ys + YS_PAD;                         // [256]

    const float* xrow = x + b * LEN;
    int gx0 = chunk * (CH_OUTS * PSTRIDE) - 400;
    int gy0 = chunk * (CH_OUTS * PSTRIDE) - 200;

    for (int i = tid; i < XS_N; i += 256) {
        int g = gx0 + i;
        xs[i] = (g >= 0 && g < LEN) ? xrow[g] : 0.f;
    }
    for (int i = tid; i < FPAD; i += 256) {
        fsh[i] = d_filt2[f * FPAD + i];
        win[i] = (i < KS) ? d_win[f * KS + i] : 0.f;
    }
    __syncthreads();

    int klo = d_klo[f], kend = d_kend[f];

    // fully unrolled passes with compile-time base offsets
    conv_pass<RPT>(xs, fsh, ys, 0 * PASS_W + tid * RPT, gy0, klo, kend);
    conv_pass<RPT>(xs, fsh, ys, 1 * PASS_W + tid * RPT, gy0, klo, kend);
    conv_pass<RPT>(xs, fsh, ys, 2 * PASS_W + tid * RPT, gy0, klo, kend);
    conv_pass<RPT>(xs, fsh, ys, 3 * PASS_W + tid * RPT, gy0, klo, kend);
    conv_pass<5>(xs, fsh, ys, TAIL_BASE + tid * 5, gy0, klo, kend);
    __syncthreads();

    // ---- pooling: 4 threads per output, taps split 101/101/101/98 ------------
    {
        int q = tid >> 6, o = tid & 63, lane = tid & 31;
        int kbase = q * 101;
        int cnt = (q == 3) ? 98 : 101;
        int off = o * PSTRIDE;
        float acc = 0.f;
        int kk = lane % cnt;
        for (int jj = 0; jj < cnt; jj++) {
            int k = kbase + kk;
            acc = fmaf(win[k], ys[off + k], acc);
            kk++;
            if (kk == cnt) kk = 0;
        }
        part[tid] = acc;
    }
    __syncthreads();
    if (tid < CH_OUTS) {
        int t = chunk * CH_OUTS + tid;
        if (t < T_OUT)
            d_frames[(b * NF + f) * T_OUT + t] =
                (part[tid] + part[tid + 64]) + (part[tid + 128] + part[tid + 192]);
    }
}

// ---------------- Kernel D: parallel EMA scan (warp per row) ----------------
__global__ void pcen_scan() {
    int row = blockIdx.x;
    int lane = threadIdx.x;
    const float* Fp = d_frames + row * T_OUT;
    float* Mp = d_Ms + row * T_OUT;

    int start = lane * 32;
    int n = T_OUT - start;
    if (n > 32) n = 32;
    if (n < 0) n = 0;

    float Bv = 0.f, Av = 1.f;
    for (int j = 0; j < n; j++) {
        Bv = fmaf(0.96f, Bv, 0.04f * Fp[start + j]);
        Av *= 0.96f;
    }
    for (int d = 1; d < 32; d <<= 1) {
        float Ap = __shfl_up_sync(0xffffffffu, Av, d);
        float Bp = __shfl_up_sync(0xffffffffu, Bv, d);
        if (lane >= d) {
            Bv = fmaf(Av, Bp, Bv);
            Av *= Ap;
        }
    }
    float Min = __shfl_up_sync(0xffffffffu, Bv, 1);
    if (lane == 0) Min = 0.f;

    float M = Min;
    for (int j = 0; j < n; j++) {
        M = fmaf(0.96f, M, 0.04f * Fp[start + j]);
        Mp[start + j] = M;
    }
}

// ---------------- Kernel E: GRU controller + PCEN output ----------------
#define EBS 128
__global__ __launch_bounds__(EBS) void pcen_ctrl(
    const float* __restrict__ w_ih, const float* __restrict__ w_hh,
    const float* __restrict__ b_ih, const float* __restrict__ b_hh,
    const float* __restrict__ hw1, const float* __restrict__ hb1,
    const float* __restrict__ hw2, const float* __restrict__ hb2,
    float* __restrict__ out) {
    __shared__ __align__(16) float whh_s[96 * 32];
    __shared__ float wih_s[96], bih_s[96], bhh_s[96];
    __shared__ __align__(16) float hw1t_s[32 * 32];  // transposed [k][m]
    __shared__ float hb1_s[32], hw2_s[64], hb2_s[2];
    __shared__ float h2s[32 * EBS];
    int tid = threadIdx.x;
    for (int i = tid; i < 3072; i += EBS) whh_s[i] = w_hh[i];
    for (int i = tid; i < 96; i += EBS) {
        wih_s[i] = w_ih[i]; bih_s[i] = b_ih[i]; bhh_s[i] = b_hh[i];
    }
    for (int i = tid; i < 1024; i += EBS) {
        int k = i >> 5, m = i & 31;
        hw1t_s[i] = hw1[m * 32 + k];
    }
    for (int i = tid; i < 32; i += EBS) hb1_s[i] = hb1[i];
    if (tid < 64) hw2_s[tid] = hw2[tid];
    if (tid < 2) hb2_s[tid] = hb2[tid];
    __syncthreads();

    int id = blockIdx.x * EBS + tid;        // 2500*128 = 320000 exact
    int t = id % T_OUT, bf = id / T_OUT;
    float X  = d_frames[bf * T_OUT + t];
    float Xp = d_frames[bf * T_OUT + (t ? t - 1 : 0)];
    float M  = d_Ms[id];

    float h1[32];
    #pragma unroll
    for (int j = 0; j < 32; j++) {
        float r1 = sigmoidf_(fmaf(Xp, wih_s[j], bih_s[j]) + bhh_s[j]);
        float z1 = sigmoidf_(fmaf(Xp, wih_s[32 + j], bih_s[32 + j]) + bhh_s[32 + j]);
        float n1 = tanhf_(fmaf(r1, bhh_s[64 + j], fmaf(Xp, wih_s[64 + j], bih_s[64 + j])));
        h1[j] = (1.f - z1) * n1;
    }
    #pragma unroll 1
    for (int j = 0; j < 32; j++) {
        float ar = bhh_s[j], az = bhh_s[32 + j], an = bhh_s[64 + j];
        const float4* wr = (const float4*)&whh_s[j * 32];
        const float4* wz = (const float4*)&whh_s[(32 + j) * 32];
        const float4* wn = (const float4*)&whh_s[(64 + j) * 32];
        #pragma unroll
        for (int k4 = 0; k4 < 8; k4++) {
            float4 a = wr[k4], bb = wz[k4], c = wn[k4];
            ar = fmaf(a.x, h1[4*k4], ar);   ar = fmaf(a.y, h1[4*k4+1], ar);
            ar = fmaf(a.z, h1[4*k4+2], ar); ar = fmaf(a.w, h1[4*k4+3], ar);
            az = fmaf(bb.x, h1[4*k4], az);   az = fmaf(bb.y, h1[4*k4+1], az);
            az = fmaf(bb.z, h1[4*k4+2], az); az = fmaf(bb.w, h1[4*k4+3], az);
            an = fmaf(c.x, h1[4*k4], an);   an = fmaf(c.y, h1[4*k4+1], an);
            an = fmaf(c.z, h1[4*k4+2], an); an = fmaf(c.w, h1[4*k4+3], an);
        }
        float r = sigmoidf_(fmaf(X, wih_s[j], bih_s[j]) + ar);
        float z = sigmoidf_(fmaf(X, wih_s[32 + j], bih_s[32 + j]) + az);
        float n = tanhf_(fmaf(r, an, fmaf(X, wih_s[64 + j], bih_s[64 + j])));
        h2s[j * EBS + tid] = (1.f - z) * n + z * h1[j];
    }
    __syncwarp();

    float hacc[32];
    #pragma unroll
    for (int m = 0; m < 32; m++) hacc[m] = hb1_s[m];
    #pragma unroll 1
    for (int k = 0; k < 32; k++) {
        float xk = h2s[k * EBS + tid];
        const float4* wt = (const float4*)&hw1t_s[k * 32];
        #pragma unroll
        for (int m4 = 0; m4 < 8; m4++) {
            float4 v = wt[m4];
            hacc[4*m4]   = fmaf(v.x, xk, hacc[4*m4]);
            hacc[4*m4+1] = fmaf(v.y, xk, hacc[4*m4+1]);
            hacc[4*m4+2] = fmaf(v.z, xk, hacc[4*m4+2]);
            hacc[4*m4+3] = fmaf(v.w, xk, hacc[4*m4+3]);
        }
    }
    float la = hb2_s[0], lb = hb2_s[1];
    #pragma unroll
    for (int m = 0; m < 32; m++) {
        float hid = fmaxf(hacc[m], 0.f);
        la = fmaf(hw2_s[m], hid, la);
        lb = fmaf(hw2_s[32 + m], hid, lb);
    }
    float alpha = sigmoidf_(la);
    float rr = fmaf(0.8f, sigmoidf_(lb), 0.2f);
    float mp = __expf(alpha * __logf(M + 1e-6f));
    float base = __fdividef(X, mp) + 2.f;
    out[id] = __expf(rr * __logf(base)) - __expf(rr * 0.6931471805599453f);
}

// ---------------- launch ----------------
extern "C" void kernel_launch(void* const* d_in, const int* in_sizes, int n_in,
                              void* d_out, int out_size) {
    const float* x    = (const float*)d_in[0];
    const float* cf   = (const float*)d_in[1];
    const float* bw   = (const float*)d_in[2];
    const float* pw   = (const float*)d_in[3];
    const float* w_ih = (const float*)d_in[4];
    const float* w_hh = (const float*)d_in[5];
    const float* b_ih = (const float*)d_in[6];
    const float* b_hh = (const float*)d_in[7];
    const float* hw1  = (const float*)d_in[8];
    const float* hb1  = (const float*)d_in[9];
    const float* hw2  = (const float*)d_in[10];
    const float* hb2  = (const float*)d_in[11];
    float* out = (float*)d_out;

    const int SMEM_BYTES = (XS_N + 3 * FPAD + YS_PAD + 256) * 4;  // 92,032 B
    cudaFuncSetAttribute(gabor_fused,
                         cudaFuncAttributeMaxDynamicSharedMemorySize, SMEM_BYTES);

    build_filters<<<NF, 256>>>(cf, bw, pw);
    gabor_fused<<<dim3(N_CHUNK, NF, NB), 256, SMEM_BYTES>>>(x);
    pcen_scan<<<NB * NF, 32>>>();
    pcen_ctrl<<<(NB * NF * T_OUT) / EBS, EBS>>>(w_ih, w_hh, b_ih, b_hh,
                                                hw1, hb1, hw2, hb2, out);
}

// round 16
// speedup vs baseline: 1.2011x; 1.0040x over previous
#include <cuda_runtime.h>

#define NF 40
#define KS 401
#define LEN 160000
#define NB 8
#define T_OUT 1000
#define PSTRIDE 160
#define RPT 12
#define FPAD 416

// fused-kernel geometry: 64 pool outputs per chunk
#define CH_OUTS 64
#define N_CHUNK 16                       // 16*64 = 1024 >= 1000
#define YS_N 10481                       // 64*160 + 401 - 160
#define YS_PAD 10496
#define XS_N 11008
#define PASS_W (256 * RPT)               // 3072 outputs per full pass
#define TAIL_BASE (3 * PASS_W)           // 9216; tail R=5 covers [9216,10496) exactly

typedef unsigned long long ull;

// ---------------- device scratch ----------------
__device__ float  d_frames[NB * NF * T_OUT];
__device__ float  d_Ms[NB * NF * T_OUT];
__device__ float2 d_filt2[NF * FPAD];
__device__ float  d_win[NF * KS];
__device__ int    d_klo[NF], d_kend[NF];

// ---------------- helpers ----------------
__device__ __forceinline__ ull ffma2(ull a, ull b, ull c) {
    ull d;
    asm("fma.rn.f32x2 %0, %1, %2, %3;" : "=l"(d) : "l"(a), "l"(b), "l"(c));
    return d;
}
__device__ __forceinline__ ull dup2(float v) {
    ull d;
    asm("mov.b64 %0, {%1, %1};" : "=l"(d) : "f"(v));
    return d;
}
__device__ __forceinline__ void unpack2(ull a, float& lo, float& hi) {
    asm("mov.b64 {%0, %1}, %2;" : "=f"(lo), "=f"(hi) : "l"(a));
}
__device__ __forceinline__ float sigmoidf_(float x) {
    return __fdividef(1.f, 1.f + __expf(-x));
}
__device__ __forceinline__ float tanhf_(float x) {
    return 1.f - __fdividef(2.f, __expf(2.f * x) + 1.f);
}

// ---------------- Kernel A: build filters ----------------
__global__ void build_filters(const float* __restrict__ cfr,
                              const float* __restrict__ bwr,
                              const float* __restrict__ pwr) {
    int f = blockIdx.x, tid = threadIdx.x;
    const float Z = 0.3747739708f;
    const float PI_F = 3.14159265358979f;
    float cf = fminf(fmaxf(cfr[f], 0.f), PI_F);
    float bw = fminf(fmaxf(bwr[f], 4.f * Z), 401.f * Z);
    float pw = fminf(fmaxf(pwr[f], 2.f / 401.f), 0.5f);
    float denom = 1.f / (sqrtf(2.f * PI_F) * bw);
    float inv2bw2 = 1.f / (2.f * bw * bw);
    float invpw = 1.f / pw;

    int R = (int)ceilf(3.5f * bw);       // 3.5 sigma truncation (rel ~1.4e-4)
    if (R > 200) R = 200;
    int klo = 200 - R, khi = 200 + R;

    for (int i = tid; i < FPAD; i += blockDim.x)
        d_filt2[f * FPAD + i] = make_float2(0.f, 0.f);
    __syncthreads();
    for (int k = tid; k < KS; k += blockDim.x) {
        float t = (float)(k - 200);
        float tt = (float)k / 400.f - 0.5f;
        d_win[f * KS + k] = expf(-0.5f * tt * tt * invpw * invpw);
        if (k >= klo && k <= khi) {
            float g = expf(-t * t * inv2bw2);
            float s, c;
            sincosf(cf * t, &s, &c);
            d_filt2[f * FPAD + k] = make_float2(denom * g * c, denom * g * s);
        }
    }
    if (tid == 0) {
        int klo_al = klo - (klo % RPT);
        int kend = klo_al + RPT * ((khi - klo_al) / RPT + 1);  // ≤ 408 < FPAD
        d_klo[f] = klo_al;
        d_kend[f] = kend;
    }
}

// ---------------- conv pass (templated output-group width) ----------------
// Loop steps by template R; (kend-klo) is a multiple of RPT (=12).
// For the R=5 tail the final group may extend past kend into the zero padding
// of fsh (FPAD=416 ≥ kend+4) — contributes exact zeros. xs reads stay < XS_N.
template <int R>
__device__ __forceinline__ void conv_pass(const float* __restrict__ xs,
                                          const float2* __restrict__ fsh,
                                          float* __restrict__ ys,
                                          int i0, int gy0, int klo, int kend) {
    int g0 = gy0 + i0;
    if (g0 >= LEN) {
        #pragma unroll
        for (int r = 0; r < R; r++)
            if (i0 + r < YS_N) ys[i0 + r] = 0.f;
        return;
    }
    ull w[R], acc[R];
    #pragma unroll
    for (int r = 0; r < R; r++) {
        acc[r] = 0ull;
        w[r] = dup2(xs[i0 + klo + r]);
    }
    for (int k = klo; k < kend; k += R) {
        #pragma unroll
        for (int j = 0; j < R; j++) {
            ull fv = *(const ull*)&fsh[k + j];
            #pragma unroll
            for (int r = 0; r < R; r++)
                acc[r] = ffma2(w[(j + r) % R], fv, acc[r]);
            w[j] = dup2(xs[i0 + k + j + R]);
        }
    }
    #pragma unroll
    for (int r = 0; r < R; r++) {
        int i = i0 + r;
        if (i < YS_N) {
            int g = g0 + r;
            float re, im;
            unpack2(acc[r], re, im);
            ys[i] = (g >= 0 && g < LEN) ? (re * re + im * im) : 0.f;
        }
    }
}

// ---------------- Kernel B: fused Gabor conv + |.|^2 + Gaussian pooling --------
__global__ __launch_bounds__(256, 2) void gabor_fused(const float* __restrict__ x) {
    int chunk = blockIdx.x, f = blockIdx.y, b = blockIdx.z;
    int tid = threadIdx.x;

    extern __shared__ __align__(16) float smem_f[];
    float*  xs   = smem_f;                              // [XS_N]
    float2* fsh  = (float2*)(smem_f + XS_N);            // [FPAD]
    float*  win  = smem_f + XS_N + 2 * FPAD;            // [FPAD]
    float*  ys   = smem_f + XS_N + 3 * FPAD;            // [YS_PAD]
    float*  part = ys + YS_PAD;                         // [256]

    const float* xrow = x + b * LEN;
    int gx0 = chunk * (CH_OUTS * PSTRIDE) - 400;
    int gy0 = chunk * (CH_OUTS * PSTRIDE) - 200;

    for (int i = tid; i < XS_N; i += 256) {
        int g = gx0 + i;
        xs[i] = (g >= 0 && g < LEN) ? xrow[g] : 0.f;
    }
    for (int i = tid; i < FPAD; i += 256) {
        fsh[i] = d_filt2[f * FPAD + i];
        win[i] = (i < KS) ? d_win[f * KS + i] : 0.f;
    }
    __syncthreads();

    int klo = d_klo[f], kend = d_kend[f];

    // fully unrolled passes with compile-time base offsets
    conv_pass<RPT>(xs, fsh, ys, 0 * PASS_W + tid * RPT, gy0, klo, kend);
    conv_pass<RPT>(xs, fsh, ys, 1 * PASS_W + tid * RPT, gy0, klo, kend);
    conv_pass<RPT>(xs, fsh, ys, 2 * PASS_W + tid * RPT, gy0, klo, kend);
    conv_pass<5>(xs, fsh, ys, TAIL_BASE + tid * 5, gy0, klo, kend);
    __syncthreads();

    // ---- pooling: 4 threads per output, taps split 101/101/101/98 ------------
    {
        int q = tid >> 6, o = tid & 63, lane = tid & 31;
        int kbase = q * 101;
        int cnt = (q == 3) ? 98 : 101;
        int off = o * PSTRIDE;
        float acc = 0.f;
        int kk = lane % cnt;
        for (int jj = 0; jj < cnt; jj++) {
            int k = kbase + kk;
            acc = fmaf(win[k], ys[off + k], acc);
            kk++;
            if (kk == cnt) kk = 0;
        }
        part[tid] = acc;
    }
    __syncthreads();
    if (tid < CH_OUTS) {
        int t = chunk * CH_OUTS + tid;
        if (t < T_OUT)
            d_frames[(b * NF + f) * T_OUT + t] =
                (part[tid] + part[tid + 64]) + (part[tid + 128] + part[tid + 192]);
    }
}

// ---------------- Kernel D: parallel EMA scan (warp per row) ----------------
__global__ void pcen_scan() {
    int row = blockIdx.x;
    int lane = threadIdx.x;
    const float* Fp = d_frames + row * T_OUT;
    float* Mp = d_Ms + row * T_OUT;

    int start = lane * 32;
    int n = T_OUT - start;
    if (n > 32) n = 32;
    if (n < 0) n = 0;

    float Bv = 0.f, Av = 1.f;
    for (int j = 0; j < n; j++) {
        Bv = fmaf(0.96f, Bv, 0.04f * Fp[start + j]);
        Av *= 0.96f;
    }
    for (int d = 1; d < 32; d <<= 1) {
        float Ap = __shfl_up_sync(0xffffffffu, Av, d);
        float Bp = __shfl_up_sync(0xffffffffu, Bv, d);
        if (lane >= d) {
            Bv = fmaf(Av, Bp, Bv);
            Av *= Ap;
        }
    }
    float Min = __shfl_up_sync(0xffffffffu, Bv, 1);
    if (lane == 0) Min = 0.f;

    float M = Min;
    for (int j = 0; j < n; j++) {
        M = fmaf(0.96f, M, 0.04f * Fp[start + j]);
        Mp[start + j] = M;
    }
}

// ---------------- Kernel E: GRU controller + PCEN output ----------------
#define EBS 128
__global__ __launch_bounds__(EBS) void pcen_ctrl(
    const float* __restrict__ w_ih, const float* __restrict__ w_hh,
    const float* __restrict__ b_ih, const float* __restrict__ b_hh,
    const float* __restrict__ hw1, const float* __restrict__ hb1,
    const float* __restrict__ hw2, const float* __restrict__ hb2,
    float* __restrict__ out) {
    __shared__ __align__(16) float whh_s[96 * 32];
    __shared__ float wih_s[96], bih_s[96], bhh_s[96];
    __shared__ __align__(16) float hw1t_s[32 * 32];  // transposed [k][m]
    __shared__ float hb1_s[32], hw2_s[64], hb2_s[2];
    __shared__ float h2s[32 * EBS];
    int tid = threadIdx.x;
    for (int i = tid; i < 3072; i += EBS) whh_s[i] = w_hh[i];
    for (int i = tid; i < 96; i += EBS) {
        wih_s[i] = w_ih[i]; bih_s[i] = b_ih[i]; bhh_s[i] = b_hh[i];
    }
    for (int i = tid; i < 1024; i += EBS) {
        int k = i >> 5, m = i & 31;
        hw1t_s[i] = hw1[m * 32 + k];
    }
    for (int i = tid; i < 32; i += EBS) hb1_s[i] = hb1[i];
    if (tid < 64) hw2_s[tid] = hw2[tid];
    if (tid < 2) hb2_s[tid] = hb2[tid];
    __syncthreads();

    int id = blockIdx.x * EBS + tid;        // 2500*128 = 320000 exact
    int t = id % T_OUT, bf = id / T_OUT;
    float X  = d_frames[bf * T_OUT + t];
    float Xp = d_frames[bf * T_OUT + (t ? t - 1 : 0)];
    float M  = d_Ms[id];

    float h1[32];
    #pragma unroll
    for (int j = 0; j < 32; j++) {
        float r1 = sigmoidf_(fmaf(Xp, wih_s[j], bih_s[j]) + bhh_s[j]);
        float z1 = sigmoidf_(fmaf(Xp, wih_s[32 + j], bih_s[32 + j]) + bhh_s[32 + j]);
        float n1 = tanhf_(fmaf(r1, bhh_s[64 + j], fmaf(Xp, wih_s[64 + j], bih_s[64 + j])));
        h1[j] = (1.f - z1) * n1;
    }
    #pragma unroll 1
    for (int j = 0; j < 32; j++) {
        float ar = bhh_s[j], az = bhh_s[32 + j], an = bhh_s[64 + j];
        const float4* wr = (const float4*)&whh_s[j * 32];
        const float4* wz = (const float4*)&whh_s[(32 + j) * 32];
        const float4* wn = (const float4*)&whh_s[(64 + j) * 32];
        #pragma unroll
        for (int k4 = 0; k4 < 8; k4++) {
            float4 a = wr[k4], bb = wz[k4], c = wn[k4];
            ar = fmaf(a.x, h1[4*k4], ar);   ar = fmaf(a.y, h1[4*k4+1], ar);
            ar = fmaf(a.z, h1[4*k4+2], ar); ar = fmaf(a.w, h1[4*k4+3], ar);
            az = fmaf(bb.x, h1[4*k4], az);   az = fmaf(bb.y, h1[4*k4+1], az);
            az = fmaf(bb.z, h1[4*k4+2], az); az = fmaf(bb.w, h1[4*k4+3], az);
            an = fmaf(c.x, h1[4*k4], an);   an = fmaf(c.y, h1[4*k4+1], an);
            an = fmaf(c.z, h1[4*k4+2], an); an = fmaf(c.w, h1[4*k4+3], an);
        }
        float r = sigmoidf_(fmaf(X, wih_s[j], bih_s[j]) + ar);
        float z = sigmoidf_(fmaf(X, wih_s[32 + j], bih_s[32 + j]) + az);
        float n = tanhf_(fmaf(r, an, fmaf(X, wih_s[64 + j], bih_s[64 + j])));
        h2s[j * EBS + tid] = (1.f - z) * n + z * h1[j];
    }
    __syncwarp();

    float hacc[32];
    #pragma unroll
    for (int m = 0; m < 32; m++) hacc[m] = hb1_s[m];
    #pragma unroll 1
    for (int k = 0; k < 32; k++) {
        float xk = h2s[k * EBS + tid];
        const float4* wt = (const float4*)&hw1t_s[k * 32];
        #pragma unroll
        for (int m4 = 0; m4 < 8; m4++) {
            float4 v = wt[m4];
            hacc[4*m4]   = fmaf(v.x, xk, hacc[4*m4]);
            hacc[4*m4+1] = fmaf(v.y, xk, hacc[4*m4+1]);
            hacc[4*m4+2] = fmaf(v.z, xk, hacc[4*m4+2]);
            hacc[4*m4+3] = fmaf(v.w, xk, hacc[4*m4+3]);
        }
    }
    float la = hb2_s[0], lb = hb2_s[1];
    #pragma unroll
    for (int m = 0; m < 32; m++) {
        float hid = fmaxf(hacc[m], 0.f);
        la = fmaf(hw2_s[m], hid, la);
        lb = fmaf(hw2_s[32 + m], hid, lb);
    }
    float alpha = sigmoidf_(la);
    float rr = fmaf(0.8f, sigmoidf_(lb), 0.2f);
    float mp = __expf(alpha * __logf(M + 1e-6f));
    float base = __fdividef(X, mp) + 2.f;
    out[id] = __expf(rr * __logf(base)) - __expf(rr * 0.6931471805599453f);
}

// ---------------- launch ----------------
extern "C" void kernel_launch(void* const* d_in, const int* in_sizes, int n_in,
                              void* d_out, int out_size) {
    const float* x    = (const float*)d_in[0];
    const float* cf   = (const float*)d_in[1];
    const float* bw   = (const float*)d_in[2];
    const float* pw   = (const float*)d_in[3];
    const float* w_ih = (const float*)d_in[4];
    const float* w_hh = (const float*)d_in[5];
    const float* b_ih = (const float*)d_in[6];
    const float* b_hh = (const float*)d_in[7];
    const float* hw1  = (const float*)d_in[8];
    const float* hb1  = (const float*)d_in[9];
    const float* hw2  = (const float*)d_in[10];
    const float* hb2  = (const float*)d_in[11];
    float* out = (float*)d_out;

    const int SMEM_BYTES = (XS_N + 3 * FPAD + YS_PAD + 256) * 4;  // 92,032 B
    cudaFuncSetAttribute(gabor_fused,
                         cudaFuncAttributeMaxDynamicSharedMemorySize, SMEM_BYTES);

    build_filters<<<NF, 256>>>(cf, bw, pw);
    gabor_fused<<<dim3(N_CHUNK, NF, NB), 256, SMEM_BYTES>>>(x);
    pcen_scan<<<NB * NF, 32>>>();
    pcen_ctrl<<<(NB * NF * T_OUT) / EBS, EBS>>>(w_ih, w_hh, b_ih, b_hh,
                                                hw1, hb1, hw2, hb2, out);
}